// round 3
// baseline (speedup 1.0000x reference)
#include <cuda_runtime.h>
#include <cstdint>

// Problem constants
#define BB   32
#define NN   1000
#define DIN  64
#define HH   128
#define AA   10
#define RB   (BB*NN)          // 32000 rows
#define MAXJ 128              // max neighbors per row (mean ~21, +24 sigma safe)

// ---------------- scratch (static device globals; no runtime alloc) ----------------
__device__ float g_h [RB*HH];      // current hidden [32000,128]
__device__ float g_t [RB*HH];      // attention output scratch
__device__ float g_v [RB*HH];
__device__ float g_q [RB*HH];
__device__ float g_k [RB*HH];
__device__ float g_g1[RB*3*HH];    // GRU gx [32000,384]
__device__ float g_g2[RB*3*HH];    // GRU gh
__device__ int   g_adj[RB*MAXJ];
__device__ int   g_cnt[RB];

// ---------------- adjacency build: 1 warp per (b,i) row ----------------
__global__ void build_adj_kernel(const float* __restrict__ mask) {
    int warp = (blockIdx.x * blockDim.x + threadIdx.x) >> 5;
    int lane = threadIdx.x & 31;
    if (warp >= RB) return;
    const float* row = mask + (size_t)warp * NN;
    int cnt = 0;
    for (int j0 = 0; j0 < NN; j0 += 32) {
        int j = j0 + lane;
        bool on = (j < NN) && (row[j] > 0.5f);
        unsigned bal = __ballot_sync(0xffffffffu, on);
        if (on) {
            int pos = cnt + __popc(bal & ((1u << lane) - 1u));
            if (pos < MAXJ) g_adj[warp * MAXJ + pos] = j;
        }
        cnt += __popc(bal);
    }
    if (lane == 0) g_cnt[warp] = min(cnt, MAXJ);
}

// ---------------- sparse masked attention: 1 warp per query row, online softmax ----
__global__ void spattn_kernel(const float* __restrict__ Q,
                              const float* __restrict__ Km,
                              const float* __restrict__ V,
                              float* __restrict__ out) {
    int warp = (blockIdx.x * blockDim.x + threadIdx.x) >> 5;
    int lane = threadIdx.x & 31;
    if (warp >= RB) return;
    int base = (warp / NN) * NN;   // batch row base
    float4 q4 = *(const float4*)(Q + (size_t)warp * HH + lane * 4);
    int cnt = g_cnt[warp];
    const int* adj = g_adj + warp * MAXJ;
    float m = -3.4e38f, l = 0.f;
    float4 acc = make_float4(0.f, 0.f, 0.f, 0.f);
    for (int t = 0; t < cnt; ++t) {
        int j = base + adj[t];
        float4 k4 = *(const float4*)(Km + (size_t)j * HH + lane * 4);
        float p = q4.x*k4.x + q4.y*k4.y + q4.z*k4.z + q4.w*k4.w;
        #pragma unroll
        for (int o = 16; o > 0; o >>= 1) p += __shfl_xor_sync(0xffffffffu, p, o);
        float4 v4 = *(const float4*)(V + (size_t)j * HH + lane * 4);
        float nm = fmaxf(m, p);
        float sc = __expf(m - nm);   // 0 on first iter (m=-3.4e38)
        float e  = __expf(p - nm);
        l = l * sc + e;
        acc.x = acc.x * sc + e * v4.x;
        acc.y = acc.y * sc + e * v4.y;
        acc.z = acc.z * sc + e * v4.z;
        acc.w = acc.w * sc + e * v4.w;
        m = nm;
    }
    float inv = 1.f / l;
    float4 o4 = make_float4(acc.x*inv, acc.y*inv, acc.z*inv, acc.w*inv);
    *(float4*)(out + (size_t)warp * HH + lane * 4) = o4;
}

// ---------------- tiled SGEMM: C[M,N] = op(A[M,K] x B) + bias, optional relu -------
// TRANSB=false: B is [K,N] row-major.  TRANSB=true: B is [N,K] row-major (C = A B^T).
// Requires: M%64==0, N%64==0, K%16==0.
template<bool TRANSB, bool RELU>
__global__ __launch_bounds__(256)
void sgemm_kernel(const float* __restrict__ A, const float* __restrict__ B,
                  const float* __restrict__ bias, float* __restrict__ C,
                  int M, int N, int K) {
    const int BM = 64, BN = 64, BK = 16;
    __shared__ float As[BK][BM];
    __shared__ float Bs[BK][BN];
    int tid = threadIdx.x;
    int bm = blockIdx.y, bn = blockIdx.x;
    int tr = tid / 16;            // 0..15  -> rows tr*4..tr*4+3
    int tc = tid % 16;            // 0..15  -> cols tc*4..tc*4+3
    // A-tile load mapping (also reused for trans-B): 64 rows x 16 cols, float4 per thread
    int lr = tid / 4;             // 0..63
    int lc = (tid % 4) * 4;       // 0,4,8,12
    // normal-B load mapping: 16 rows x 64 cols
    int br = tid / 16;            // 0..15
    int bc = (tid % 16) * 4;      // 0..60

    float acc[4][4];
    #pragma unroll
    for (int i = 0; i < 4; ++i)
        #pragma unroll
        for (int j = 0; j < 4; ++j) acc[i][j] = 0.f;

    const float* Ab = A + (size_t)(bm * BM) * K;
    for (int k0 = 0; k0 < K; k0 += BK) {
        float4 av = *(const float4*)(Ab + (size_t)lr * K + k0 + lc);
        As[lc+0][lr] = av.x; As[lc+1][lr] = av.y;
        As[lc+2][lr] = av.z; As[lc+3][lr] = av.w;
        if (TRANSB) {
            float4 bv = *(const float4*)(B + (size_t)(bn * BN + lr) * K + k0 + lc);
            Bs[lc+0][lr] = bv.x; Bs[lc+1][lr] = bv.y;
            Bs[lc+2][lr] = bv.z; Bs[lc+3][lr] = bv.w;
        } else {
            float4 bv = *(const float4*)(B + (size_t)(k0 + br) * N + bn * BN + bc);
            *(float4*)&Bs[br][bc] = bv;
        }
        __syncthreads();
        #pragma unroll
        for (int kk = 0; kk < BK; ++kk) {
            float af[4], bf[4];
            *(float4*)af = *(const float4*)&As[kk][tr * 4];
            *(float4*)bf = *(const float4*)&Bs[kk][tc * 4];
            #pragma unroll
            for (int i = 0; i < 4; ++i)
                #pragma unroll
                for (int j = 0; j < 4; ++j)
                    acc[i][j] += af[i] * bf[j];
        }
        __syncthreads();
    }
    int col = bn * BN + tc * 4;
    float4 b4 = *(const float4*)(bias + col);
    #pragma unroll
    for (int i = 0; i < 4; ++i) {
        int row = bm * BM + tr * 4 + i;
        float4 r;
        r.x = acc[i][0] + b4.x; r.y = acc[i][1] + b4.y;
        r.z = acc[i][2] + b4.z; r.w = acc[i][3] + b4.w;
        if (RELU) {
            r.x = fmaxf(r.x, 0.f); r.y = fmaxf(r.y, 0.f);
            r.z = fmaxf(r.z, 0.f); r.w = fmaxf(r.w, 0.f);
        }
        *(float4*)(C + (size_t)row * N + col) = r;
    }
}

// ---------------- GRU gate fusion ----------------
__global__ void gru_gate_kernel(const float* __restrict__ g1, const float* __restrict__ g2,
                                const float* __restrict__ hin, float* __restrict__ hout) {
    int idx = blockIdx.x * blockDim.x + threadIdx.x;
    if (idx >= RB * HH) return;
    int mrow = idx >> 7;
    int k = idx & 127;
    size_t b = (size_t)mrow * (3 * HH) + k;
    float xr = g1[b],           hr = g2[b];
    float xz = g1[b + HH],      hz = g2[b + HH];
    float xn = g1[b + 2 * HH],  hn = g2[b + 2 * HH];
    float r = 1.f / (1.f + __expf(-(xr + hr)));
    float z = 1.f / (1.f + __expf(-(xz + hz)));
    float n = tanhf(xn + r * hn);
    hout[idx] = (1.f - z) * n + z * hin[idx];
}

// ---------------- FC head: [32000,128] x [128,10] + b, 1 warp per row -------------
__global__ void fc_kernel(const float* __restrict__ Hm, const float* __restrict__ W,
                          const float* __restrict__ bias, float* __restrict__ out) {
    __shared__ float Wt[AA * HH];   // transposed: Wt[a*128 + k]
    __shared__ float bs[AA];
    int tid = threadIdx.x;
    for (int i = tid; i < AA * HH; i += blockDim.x) {
        int k = i / AA, a = i % AA;
        Wt[a * HH + k] = W[i];
    }
    if (tid < AA) bs[tid] = bias[tid];
    __syncthreads();
    int warp = (blockIdx.x * blockDim.x + tid) >> 5;
    int lane = tid & 31;
    if (warp >= RB) return;
    float4 h4 = *(const float4*)(Hm + (size_t)warp * HH + lane * 4);
    #pragma unroll
    for (int a = 0; a < AA; ++a) {
        float4 w4 = *(const float4*)(Wt + a * HH + lane * 4);
        float p = h4.x*w4.x + h4.y*w4.y + h4.z*w4.z + h4.w*w4.w;
        #pragma unroll
        for (int o = 16; o > 0; o >>= 1) p += __shfl_xor_sync(0xffffffffu, p, o);
        if (lane == 0) out[warp * AA + a] = p + bs[a];
    }
}

// ---------------- launch ----------------
extern "C" void kernel_launch(void* const* d_in, const int* in_sizes, int n_in,
                              void* d_out, int out_size) {
    const float* x      = (const float*)d_in[0];
    const float* mask   = (const float*)d_in[1];
    const float* hidden = (const float*)d_in[2];
    const float* encW   = (const float*)d_in[3];
    const float* encb   = (const float*)d_in[4];
    const float* Wv1 = (const float*)d_in[5],  *bv1 = (const float*)d_in[6];
    const float* Wk1 = (const float*)d_in[7],  *bk1 = (const float*)d_in[8];
    const float* Wq1 = (const float*)d_in[9],  *bq1 = (const float*)d_in[10];
    const float* Wo1 = (const float*)d_in[11], *bo1 = (const float*)d_in[12];
    const float* Wv2 = (const float*)d_in[13], *bv2 = (const float*)d_in[14];
    const float* Wk2 = (const float*)d_in[15], *bk2 = (const float*)d_in[16];
    const float* Wq2 = (const float*)d_in[17], *bq2 = (const float*)d_in[18];
    const float* Wo2 = (const float*)d_in[19], *bo2 = (const float*)d_in[20];
    const float* Wih = (const float*)d_in[21], *bih = (const float*)d_in[22];
    const float* Whh = (const float*)d_in[23], *bhh = (const float*)d_in[24];
    const float* fcW = (const float*)d_in[25], *fcb = (const float*)d_in[26];

    float* out = (float*)d_out;
    float* qout = out;
    float* hout = out + (size_t)RB * AA;   // (q_out, h) concatenated

    float *ph, *pt, *pv, *pq, *pk, *pg1, *pg2;
    cudaGetSymbolAddress((void**)&ph,  g_h);
    cudaGetSymbolAddress((void**)&pt,  g_t);
    cudaGetSymbolAddress((void**)&pv,  g_v);
    cudaGetSymbolAddress((void**)&pq,  g_q);
    cudaGetSymbolAddress((void**)&pk,  g_k);
    cudaGetSymbolAddress((void**)&pg1, g_g1);
    cudaGetSymbolAddress((void**)&pg2, g_g2);

    dim3 gridN128(HH / 64, RB / 64);        // (2, 500)
    dim3 gridN384(3 * HH / 64, RB / 64);    // (6, 500)
    const int WB = 256;
    const int rowBlocks = RB / (WB / 32);   // 4000 (warp-per-row kernels)

    // adjacency from mask (shared by both attention layers)
    build_adj_kernel<<<rowBlocks, WB>>>(mask);

    // encoder: h1 = relu(x @ encW + encb)
    sgemm_kernel<false, true><<<gridN128, WB>>>(x, encW, encb, ph, RB, HH, DIN);

    // ---- attention layer 1 ----
    sgemm_kernel<false, true><<<gridN128, WB>>>(ph, Wv1, bv1, pv, RB, HH, HH);
    sgemm_kernel<false, true><<<gridN128, WB>>>(ph, Wq1, bq1, pq, RB, HH, HH);
    sgemm_kernel<false, true><<<gridN128, WB>>>(ph, Wk1, bk1, pk, RB, HH, HH);
    spattn_kernel<<<rowBlocks, WB>>>(pq, pk, pv, pt);
    sgemm_kernel<false, true><<<gridN128, WB>>>(pt, Wo1, bo1, ph, RB, HH, HH);

    // ---- attention layer 2 ----
    sgemm_kernel<false, true><<<gridN128, WB>>>(ph, Wv2, bv2, pv, RB, HH, HH);
    sgemm_kernel<false, true><<<gridN128, WB>>>(ph, Wq2, bq2, pq, RB, HH, HH);
    sgemm_kernel<false, true><<<gridN128, WB>>>(ph, Wk2, bk2, pk, RB, HH, HH);
    spattn_kernel<<<rowBlocks, WB>>>(pq, pk, pv, pt);
    sgemm_kernel<false, true><<<gridN128, WB>>>(pt, Wo2, bo2, ph, RB, HH, HH);

    // ---- GRU: gx = obs @ Wih^T + bih ; gh = hin @ Whh^T + bhh ----
    sgemm_kernel<true, false><<<gridN384, WB>>>(ph, Wih, bih, pg1, RB, 3 * HH, HH);
    sgemm_kernel<true, false><<<gridN384, WB>>>(hidden, Whh, bhh, pg2, RB, 3 * HH, HH);
    gru_gate_kernel<<<(RB * HH + WB - 1) / WB, WB>>>(pg1, pg2, hidden, hout);

    // ---- head: q_out = h @ fcW + fcb ----
    fc_kernel<<<rowBlocks, WB>>>(hout, fcW, fcb, qout);
    (void)in_sizes; (void)n_in; (void)out_size;
}

// round 4
// speedup vs baseline: 1.1203x; 1.1203x over previous
#include <cuda_runtime.h>
#include <cstdint>

// Problem constants
#define BB   32
#define NN   1000
#define DIN  64
#define HH   128
#define AA   10
#define RB   (BB*NN)          // 32000 rows
#define MAXJ 128              // max neighbors per row (mean ~21)

// ---------------- scratch (static device globals; no runtime alloc) ----------------
__device__ float g_h  [RB*HH];       // current hidden [32000,128]
__device__ float g_t  [RB*HH];       // attention output scratch
__device__ float g_g1 [RB*3*HH];     // vqk packed output / GRU gx [32000,384]
__device__ float g_g2 [RB*3*HH];     // GRU gh
__device__ float g_wp1[HH*3*HH];     // packed vqk weights layer1 [128,384]
__device__ float g_wp2[HH*3*HH];
__device__ float g_bp1[3*HH];
__device__ float g_bp2[3*HH];
__device__ int   g_adj[RB*MAXJ];
__device__ int   g_cnt[RB];

// ---------------- weight pack: [v|q|k] -> [128,384] ----------------
__global__ void pack_vqk_kernel(const float* __restrict__ Wv, const float* __restrict__ Wq,
                                const float* __restrict__ Wk, const float* __restrict__ bv,
                                const float* __restrict__ bq, const float* __restrict__ bk,
                                float* __restrict__ Wp, float* __restrict__ bp) {
    int i = blockIdx.x * blockDim.x + threadIdx.x;
    if (i < HH * HH) {
        int k = i >> 7, n = i & 127;
        Wp[k * 384 + n]       = Wv[i];
        Wp[k * 384 + 128 + n] = Wq[i];
        Wp[k * 384 + 256 + n] = Wk[i];
    }
    if (i < HH) { bp[i] = bv[i]; bp[128 + i] = bq[i]; bp[256 + i] = bk[i]; }
}

// ---------------- adjacency build: 1 warp per (b,i) row ----------------
__global__ void build_adj_kernel(const float* __restrict__ mask) {
    int warp = (blockIdx.x * blockDim.x + threadIdx.x) >> 5;
    int lane = threadIdx.x & 31;
    if (warp >= RB) return;
    const float* row = mask + (size_t)warp * NN;
    int cnt = 0;
    for (int j0 = 0; j0 < NN; j0 += 32) {
        int j = j0 + lane;
        bool on = (j < NN) && (row[j] > 0.5f);
        unsigned bal = __ballot_sync(0xffffffffu, on);
        if (on) {
            int pos = cnt + __popc(bal & ((1u << lane) - 1u));
            if (pos < MAXJ) g_adj[warp * MAXJ + pos] = j;
        }
        cnt += __popc(bal);
    }
    if (lane == 0) g_cnt[warp] = min(cnt, MAXJ);
}

// ------- sparse attention over packed [32000,384] vqk buffer (v|q|k), warp/row -----
__global__ void spattn_kernel(const float* __restrict__ vqk, float* __restrict__ out) {
    int warp = (blockIdx.x * blockDim.x + threadIdx.x) >> 5;
    int lane = threadIdx.x & 31;
    if (warp >= RB) return;
    int base = (warp / NN) * NN;
    float4 q4 = *(const float4*)(vqk + (size_t)warp * 384 + 128 + lane * 4);
    int cnt = g_cnt[warp];
    const int* adj = g_adj + warp * MAXJ;
    float m = -3.4e38f, l = 0.f;
    float4 acc = make_float4(0.f, 0.f, 0.f, 0.f);
    for (int t = 0; t < cnt; ++t) {
        size_t j = (size_t)(base + adj[t]) * 384;
        float4 k4 = *(const float4*)(vqk + j + 256 + lane * 4);
        float p = q4.x*k4.x + q4.y*k4.y + q4.z*k4.z + q4.w*k4.w;
        #pragma unroll
        for (int o = 16; o > 0; o >>= 1) p += __shfl_xor_sync(0xffffffffu, p, o);
        float4 v4 = *(const float4*)(vqk + j + lane * 4);
        float nm = fmaxf(m, p);
        float sc = __expf(m - nm);
        float e  = __expf(p - nm);
        l = l * sc + e;
        acc.x = acc.x * sc + e * v4.x;
        acc.y = acc.y * sc + e * v4.y;
        acc.z = acc.z * sc + e * v4.z;
        acc.w = acc.w * sc + e * v4.w;
        m = nm;
    }
    float inv = 1.f / l;
    float4 o4 = make_float4(acc.x*inv, acc.y*inv, acc.z*inv, acc.w*inv);
    *(float4*)(out + (size_t)warp * HH + lane * 4) = o4;
}

// ---------------- SGEMM: BM=128, BN=64, BK=16, 256 thr, 8x4 frags -------------------
// TRANSB=false: B is [K,N] row-major.  TRANSB=true: B is [N,K] row-major (C = A B^T).
// Requires: M%128==0, N%64==0, K%16==0.
template<bool TRANSB, bool RELU>
__global__ __launch_bounds__(256)
void sgemm_kernel(const float* __restrict__ A, const float* __restrict__ B,
                  const float* __restrict__ bias, float* __restrict__ C,
                  int M, int N, int K) {
    const int BM = 128, BN = 64, BK = 16;
    __shared__ float As[BK][BM];
    __shared__ float Bs[BK][BN];
    int tid = threadIdx.x;
    int bm = blockIdx.y, bn = blockIdx.x;
    int tx = tid & 15;            // 0..15 -> cols tx*4..+3
    int ty = tid >> 4;            // 0..15 -> rows ty*4..+3 and +64
    // global load mappings
    int ar = tid >> 2;            // 0..63 -> A rows ar, ar+64  (also trans-B row n)
    int ac = (tid & 3) * 4;       // 0,4,8,12 (k offset)
    int br = tid >> 4;            // normal-B: row k (0..15)
    int bc = (tid & 15) * 4;      // normal-B: col (0..60)

    const float* Ab = A + (size_t)(bm * BM) * K;

    float4 a0g = *(const float4*)(Ab + (size_t)ar * K + ac);
    float4 a1g = *(const float4*)(Ab + (size_t)(ar + 64) * K + ac);
    float4 bg;
    if (TRANSB) bg = *(const float4*)(B + (size_t)(bn * BN + ar) * K + ac);
    else        bg = *(const float4*)(B + (size_t)br * N + bn * BN + bc);

    float acc[8][4];
    #pragma unroll
    for (int i = 0; i < 8; ++i)
        #pragma unroll
        for (int j = 0; j < 4; ++j) acc[i][j] = 0.f;

    for (int k0 = 0; k0 < K; k0 += BK) {
        // stage current tile to smem
        As[ac+0][ar] = a0g.x; As[ac+1][ar] = a0g.y;
        As[ac+2][ar] = a0g.z; As[ac+3][ar] = a0g.w;
        As[ac+0][ar+64] = a1g.x; As[ac+1][ar+64] = a1g.y;
        As[ac+2][ar+64] = a1g.z; As[ac+3][ar+64] = a1g.w;
        if (TRANSB) {
            Bs[ac+0][ar] = bg.x; Bs[ac+1][ar] = bg.y;
            Bs[ac+2][ar] = bg.z; Bs[ac+3][ar] = bg.w;
        } else {
            *(float4*)&Bs[br][bc] = bg;
        }
        __syncthreads();
        // prefetch next tile into registers
        int k1 = k0 + BK;
        if (k1 < K) {
            a0g = *(const float4*)(Ab + (size_t)ar * K + k1 + ac);
            a1g = *(const float4*)(Ab + (size_t)(ar + 64) * K + k1 + ac);
            if (TRANSB) bg = *(const float4*)(B + (size_t)(bn * BN + ar) * K + k1 + ac);
            else        bg = *(const float4*)(B + (size_t)(k1 + br) * N + bn * BN + bc);
        }
        #pragma unroll
        for (int kk = 0; kk < BK; ++kk) {
            float a0[4], a1[4], bf[4];
            *(float4*)a0 = *(const float4*)&As[kk][ty * 4];
            *(float4*)a1 = *(const float4*)&As[kk][ty * 4 + 64];
            *(float4*)bf = *(const float4*)&Bs[kk][tx * 4];
            #pragma unroll
            for (int j = 0; j < 4; ++j) {
                acc[0][j] += a0[0] * bf[j];
                acc[1][j] += a0[1] * bf[j];
                acc[2][j] += a0[2] * bf[j];
                acc[3][j] += a0[3] * bf[j];
                acc[4][j] += a1[0] * bf[j];
                acc[5][j] += a1[1] * bf[j];
                acc[6][j] += a1[2] * bf[j];
                acc[7][j] += a1[3] * bf[j];
            }
        }
        __syncthreads();
    }
    int col = bn * BN + tx * 4;
    float4 b4 = *(const float4*)(bias + col);
    #pragma unroll
    for (int h = 0; h < 2; ++h) {
        #pragma unroll
        for (int i = 0; i < 4; ++i) {
            int row = bm * BM + ty * 4 + h * 64 + i;
            float4 r;
            r.x = acc[h*4+i][0] + b4.x; r.y = acc[h*4+i][1] + b4.y;
            r.z = acc[h*4+i][2] + b4.z; r.w = acc[h*4+i][3] + b4.w;
            if (RELU) {
                r.x = fmaxf(r.x, 0.f); r.y = fmaxf(r.y, 0.f);
                r.z = fmaxf(r.z, 0.f); r.w = fmaxf(r.w, 0.f);
            }
            *(float4*)(C + (size_t)row * N + col) = r;
        }
    }
}

// ---------------- GRU gate fusion ----------------
__global__ void gru_gate_kernel(const float* __restrict__ g1, const float* __restrict__ g2,
                                const float* __restrict__ hin, float* __restrict__ hout) {
    int idx = blockIdx.x * blockDim.x + threadIdx.x;
    if (idx >= RB * HH) return;
    int mrow = idx >> 7;
    int k = idx & 127;
    size_t b = (size_t)mrow * (3 * HH) + k;
    float xr = g1[b],           hr = g2[b];
    float xz = g1[b + HH],      hz = g2[b + HH];
    float xn = g1[b + 2 * HH],  hn = g2[b + 2 * HH];
    float r = 1.f / (1.f + __expf(-(xr + hr)));
    float z = 1.f / (1.f + __expf(-(xz + hz)));
    float n = tanhf(xn + r * hn);
    hout[idx] = (1.f - z) * n + z * hin[idx];
}

// ---------------- FC head: [32000,128] x [128,10] + b, 1 warp per row -------------
__global__ void fc_kernel(const float* __restrict__ Hm, const float* __restrict__ W,
                          const float* __restrict__ bias, float* __restrict__ out) {
    __shared__ float Wt[AA * HH];   // transposed: Wt[a*128 + k]
    __shared__ float bs[AA];
    int tid = threadIdx.x;
    for (int i = tid; i < AA * HH; i += blockDim.x) {
        int k = i / AA, a = i % AA;
        Wt[a * HH + k] = W[i];
    }
    if (tid < AA) bs[tid] = bias[tid];
    __syncthreads();
    int warp = (blockIdx.x * blockDim.x + tid) >> 5;
    int lane = tid & 31;
    if (warp >= RB) return;
    float4 h4 = *(const float4*)(Hm + (size_t)warp * HH + lane * 4);
    #pragma unroll
    for (int a = 0; a < AA; ++a) {
        float4 w4 = *(const float4*)(Wt + a * HH + lane * 4);
        float p = h4.x*w4.x + h4.y*w4.y + h4.z*w4.z + h4.w*w4.w;
        #pragma unroll
        for (int o = 16; o > 0; o >>= 1) p += __shfl_xor_sync(0xffffffffu, p, o);
        if (lane == 0) out[warp * AA + a] = p + bs[a];
    }
}

// ---------------- launch ----------------
extern "C" void kernel_launch(void* const* d_in, const int* in_sizes, int n_in,
                              void* d_out, int out_size) {
    const float* x      = (const float*)d_in[0];
    const float* mask   = (const float*)d_in[1];
    const float* hidden = (const float*)d_in[2];
    const float* encW   = (const float*)d_in[3];
    const float* encb   = (const float*)d_in[4];
    const float* Wv1 = (const float*)d_in[5],  *bv1 = (const float*)d_in[6];
    const float* Wk1 = (const float*)d_in[7],  *bk1 = (const float*)d_in[8];
    const float* Wq1 = (const float*)d_in[9],  *bq1 = (const float*)d_in[10];
    const float* Wo1 = (const float*)d_in[11], *bo1 = (const float*)d_in[12];
    const float* Wv2 = (const float*)d_in[13], *bv2 = (const float*)d_in[14];
    const float* Wk2 = (const float*)d_in[15], *bk2 = (const float*)d_in[16];
    const float* Wq2 = (const float*)d_in[17], *bq2 = (const float*)d_in[18];
    const float* Wo2 = (const float*)d_in[19], *bo2 = (const float*)d_in[20];
    const float* Wih = (const float*)d_in[21], *bih = (const float*)d_in[22];
    const float* Whh = (const float*)d_in[23], *bhh = (const float*)d_in[24];
    const float* fcW = (const float*)d_in[25], *fcb = (const float*)d_in[26];

    float* out = (float*)d_out;
    float* qout = out;
    float* hout = out + (size_t)RB * AA;   // (q_out, h) concatenated

    float *ph, *pt, *pg1, *pg2, *pwp1, *pwp2, *pbp1, *pbp2;
    cudaGetSymbolAddress((void**)&ph,  g_h);
    cudaGetSymbolAddress((void**)&pt,  g_t);
    cudaGetSymbolAddress((void**)&pg1, g_g1);
    cudaGetSymbolAddress((void**)&pg2, g_g2);
    cudaGetSymbolAddress((void**)&pwp1, g_wp1);
    cudaGetSymbolAddress((void**)&pwp2, g_wp2);
    cudaGetSymbolAddress((void**)&pbp1, g_bp1);
    cudaGetSymbolAddress((void**)&pbp2, g_bp2);

    dim3 gridN128(HH / 64, RB / 128);        // (2, 250)
    dim3 gridN384(3 * HH / 64, RB / 128);    // (6, 250)
    const int WB = 256;
    const int rowBlocks = RB / (WB / 32);    // 4000 (warp-per-row kernels)

    // pack vqk weights for both layers; adjacency from mask
    pack_vqk_kernel<<<(HH*HH + WB - 1)/WB, WB>>>(Wv1, Wq1, Wk1, bv1, bq1, bk1, pwp1, pbp1);
    pack_vqk_kernel<<<(HH*HH + WB - 1)/WB, WB>>>(Wv2, Wq2, Wk2, bv2, bq2, bk2, pwp2, pbp2);
    build_adj_kernel<<<rowBlocks, WB>>>(mask);

    // encoder: h1 = relu(x @ encW + encb)
    sgemm_kernel<false, true><<<gridN128, WB>>>(x, encW, encb, ph, RB, HH, DIN);

    // ---- attention layer 1: fused vqk GEMM, sparse attention, output proj ----
    sgemm_kernel<false, true><<<gridN384, WB>>>(ph, pwp1, pbp1, pg1, RB, 3*HH, HH);
    spattn_kernel<<<rowBlocks, WB>>>(pg1, pt);
    sgemm_kernel<false, true><<<gridN128, WB>>>(pt, Wo1, bo1, ph, RB, HH, HH);

    // ---- attention layer 2 ----
    sgemm_kernel<false, true><<<gridN384, WB>>>(ph, pwp2, pbp2, pg1, RB, 3*HH, HH);
    spattn_kernel<<<rowBlocks, WB>>>(pg1, pt);
    sgemm_kernel<false, true><<<gridN128, WB>>>(pt, Wo2, bo2, ph, RB, HH, HH);

    // ---- GRU: gx = obs @ Wih^T + bih ; gh = hin @ Whh^T + bhh ----
    sgemm_kernel<true, false><<<gridN384, WB>>>(ph, Wih, bih, pg1, RB, 3 * HH, HH);
    sgemm_kernel<true, false><<<gridN384, WB>>>(hidden, Whh, bhh, pg2, RB, 3 * HH, HH);
    gru_gate_kernel<<<(RB * HH + WB - 1) / WB, WB>>>(pg1, pg2, hidden, hout);

    // ---- head: q_out = h @ fcW + fcb ----
    fc_kernel<<<rowBlocks, WB>>>(hout, fcW, fcb, qout);
    (void)in_sizes; (void)n_in; (void)out_size;
}

// round 6
// speedup vs baseline: 1.6500x; 1.4728x over previous
#include <cuda_runtime.h>
#include <cuda_bf16.h>
#include <cstdint>

// Problem constants
#define BB   32
#define NN   1000
#define DIN  64
#define HH   128
#define AA   10
#define RB   (BB*NN)          // 32000 rows
#define MAXJ 128

// ======================= scratch (static device globals) ========================
__device__ float g_h  [RB*HH];
__device__ float g_t  [RB*HH];
__device__ float g_g1 [RB*3*HH];
__device__ float g_g2 [RB*3*HH];
__device__ int   g_adj[RB*MAXJ];
__device__ int   g_cnt[RB];
// fragment-packed weights: uint4 per (kstep, ntile, lane) = {bh0,bh1,bl0,bl1}
// count = (K/16) * (N/8) * 32
__device__ uint4 g_Benc[4*16*32];      // K=64,  N=128
__device__ uint4 g_Bo1 [8*16*32];      // K=128, N=128
__device__ uint4 g_Bo2 [8*16*32];
__device__ uint4 g_Bih [8*48*32];      // K=128, N=384
__device__ uint4 g_Bhh [8*48*32];
__device__ uint4 g_Bv1 [8*48*32];
__device__ uint4 g_Bv2 [8*48*32];
__device__ float g_bp1 [3*HH];
__device__ float g_bp2 [3*HH];

// ======================= helpers ================================================
__device__ __forceinline__ void bsplit(float v, uint16_t& h, uint16_t& l) {
    __nv_bfloat16 bh = __float2bfloat16(v);
    float fh = __bfloat162float(bh);
    __nv_bfloat16 bl = __float2bfloat16(v - fh);
    h = __bfloat16_as_ushort(bh);
    l = __bfloat16_as_ushort(bl);
}
__device__ __forceinline__ uint32_t pk(uint16_t lo, uint16_t hi) {
    return ((uint32_t)hi << 16) | lo;
}
#define MMA_BF16(d, a, b0, b1)                                                   \
    asm volatile("mma.sync.aligned.m16n8k16.row.col.f32.bf16.bf16.f32 "          \
                 "{%0,%1,%2,%3}, {%4,%5,%6,%7}, {%8,%9}, {%0,%1,%2,%3};"         \
                 : "+f"((d)[0]), "+f"((d)[1]), "+f"((d)[2]), "+f"((d)[3])        \
                 : "r"((a)[0]), "r"((a)[1]), "r"((a)[2]), "r"((a)[3]),           \
                   "r"(b0), "r"(b1))

// ======================= weight fragment packing ================================
// For mma m16n8k16 col-major B: b0 = {B[k0][n], B[k0+1][n]}, b1 = rows k0+8,k0+9,
// k0 = ks*16 + (lane&3)*2, n = ntile*8 + (lane>>2).
__global__ void pack_frag_kernel(const float* __restrict__ W, uint4* __restrict__ Bp,
                                 int N, int K, int transb) {
    int i = blockIdx.x * blockDim.x + threadIdx.x;
    int NT = N >> 3, KS = K >> 4;
    if (i >= KS * NT * 32) return;
    int lane = i & 31, rest = i >> 5;
    int ntg = rest % NT, ks = rest / NT;
    int n = ntg * 8 + (lane >> 2);
    int k0 = ks * 16 + (lane & 3) * 2;
    float v[4];
    #pragma unroll
    for (int j = 0; j < 4; ++j) {
        int k = k0 + (j >> 1) * 8 + (j & 1);
        v[j] = transb ? W[n * K + k] : W[k * N + n];
    }
    uint16_t h[4], l[4];
    #pragma unroll
    for (int j = 0; j < 4; ++j) bsplit(v[j], h[j], l[j]);
    Bp[i] = make_uint4(pk(h[0], h[1]), pk(h[2], h[3]), pk(l[0], l[1]), pk(l[2], l[3]));
}

__global__ void pack_vqk_frag_kernel(const float* __restrict__ Wv, const float* __restrict__ Wq,
                                     const float* __restrict__ Wk, const float* __restrict__ bv,
                                     const float* __restrict__ bq, const float* __restrict__ bk,
                                     uint4* __restrict__ Bp, float* __restrict__ bp) {
    int i = blockIdx.x * blockDim.x + threadIdx.x;
    const int NT = 48, KS = 8, K = 128;
    if (i < HH) { bp[i] = bv[i]; bp[128 + i] = bq[i]; bp[256 + i] = bk[i]; }
    if (i >= KS * NT * 32) return;
    int lane = i & 31, rest = i >> 5;
    int ntg = rest % NT, ks = rest / NT;
    int n = ntg * 8 + (lane >> 2);
    const float* W = (n < 128) ? Wv : (n < 256) ? Wq : Wk;
    int nn = n & 127;
    int k0 = ks * 16 + (lane & 3) * 2;
    float v[4];
    #pragma unroll
    for (int j = 0; j < 4; ++j) {
        int k = k0 + (j >> 1) * 8 + (j & 1);
        v[j] = W[k * K + nn];             // Wv/Wq/Wk are [K=128, N=128] row-major
    }
    uint16_t h[4], l[4];
    #pragma unroll
    for (int j = 0; j < 4; ++j) bsplit(v[j], h[j], l[j]);
    Bp[i] = make_uint4(pk(h[0], h[1]), pk(h[2], h[3]), pk(l[0], l[1]), pk(l[2], l[3]));
}

// ======================= bf16x2 tensor-core GEMM ================================
// C[32000, NTOT] = relu?(A[32000,K] x B + bias), B pre-packed fragments.
// CTA tile 128x128, grid (250, NTOT/128). 8 warps = 2m x 4n, warp tile 64x32.
template<int K, bool RELU>
__global__ __launch_bounds__(256)
void mma_gemm_kernel(const float* __restrict__ A, const uint4* __restrict__ Bp,
                     const float* __restrict__ bias, float* __restrict__ C, int NTOT) {
    constexpr int KSTEPS = K / 16, KPAIRS = K / 2, F4R = K / 4;
    extern __shared__ uint32_t sA[];                  // Ah [128*KPAIRS] | Al [128*KPAIRS]
    uint32_t* Ah = sA;
    uint32_t* Al = sA + 128 * KPAIRS;
    const int tid = threadIdx.x, lane = tid & 31, wid = tid >> 5;
    const int mrow0 = blockIdx.x * 128, ncol0 = blockIdx.y * 128;

    // ---- convert A tile fp32 -> hi/lo bf16 pairs, XOR-swizzled ----
    #pragma unroll
    for (int c = 0; c < (128 * F4R) / 256; ++c) {
        int idx = tid + c * 256;
        int r = idx / F4R, q = idx % F4R;
        float4 v = *(const float4*)(A + (size_t)(mrow0 + r) * K + q * 4);
        uint16_t h0,l0,h1,l1,h2,l2,h3,l3;
        bsplit(v.x, h0, l0); bsplit(v.y, h1, l1);
        bsplit(v.z, h2, l2); bsplit(v.w, h3, l3);
        int p0 = q * 2, sw = (r & 7) << 2, base = r * KPAIRS;
        Ah[base + (p0 ^ sw)]       = pk(h0, h1);
        Ah[base + ((p0 + 1) ^ sw)] = pk(h2, h3);
        Al[base + (p0 ^ sw)]       = pk(l0, l1);
        Al[base + ((p0 + 1) ^ sw)] = pk(l2, l3);
    }
    __syncthreads();

    const int wm = wid & 1, wn = wid >> 1;
    const int g = lane >> 2, tg = lane & 3;
    const int NTtot = NTOT >> 3;
    const int ntbase = (ncol0 >> 3) + wn * 4;

    float acc[4][4][4];
    #pragma unroll
    for (int mt = 0; mt < 4; ++mt)
        #pragma unroll
        for (int nt = 0; nt < 4; ++nt)
            #pragma unroll
            for (int j = 0; j < 4; ++j) acc[mt][nt][j] = 0.f;

    #pragma unroll
    for (int ks = 0; ks < KSTEPS; ++ks) {
        uint32_t ah[4][4], al[4][4];
        #pragma unroll
        for (int mt = 0; mt < 4; ++mt) {
            int row = wm * 64 + mt * 16 + g;
            int sw = (row & 7) << 2;                  // (row+8)&7 == row&7
            int b0 = row * KPAIRS, b8 = (row + 8) * KPAIRS;
            int p0 = ks * 8 + tg;
            ah[mt][0] = Ah[b0 + (p0 ^ sw)];
            ah[mt][1] = Ah[b8 + (p0 ^ sw)];
            ah[mt][2] = Ah[b0 + ((p0 + 4) ^ sw)];
            ah[mt][3] = Ah[b8 + ((p0 + 4) ^ sw)];
            al[mt][0] = Al[b0 + (p0 ^ sw)];
            al[mt][1] = Al[b8 + (p0 ^ sw)];
            al[mt][2] = Al[b0 + ((p0 + 4) ^ sw)];
            al[mt][3] = Al[b8 + ((p0 + 4) ^ sw)];
        }
        #pragma unroll
        for (int nt = 0; nt < 4; ++nt) {
            uint4 b = Bp[(size_t)(ks * NTtot + ntbase + nt) * 32 + lane];
            #pragma unroll
            for (int mt = 0; mt < 4; ++mt) {
                MMA_BF16(acc[mt][nt], ah[mt], b.x, b.y);   // hi*hi
                MMA_BF16(acc[mt][nt], al[mt], b.x, b.y);   // lo*hi
                MMA_BF16(acc[mt][nt], ah[mt], b.z, b.w);   // hi*lo
            }
        }
    }

    // ---- epilogue: bias (+relu) + store ----
    #pragma unroll
    for (int mt = 0; mt < 4; ++mt) {
        int row = mrow0 + wm * 64 + mt * 16 + g;
        #pragma unroll
        for (int nt = 0; nt < 4; ++nt) {
            int col = ncol0 + wn * 32 + nt * 8 + tg * 2;
            float b0 = bias[col], b1 = bias[col + 1];
            float2 v0 = make_float2(acc[mt][nt][0] + b0, acc[mt][nt][1] + b1);
            float2 v1 = make_float2(acc[mt][nt][2] + b0, acc[mt][nt][3] + b1);
            if (RELU) {
                v0.x = fmaxf(v0.x, 0.f); v0.y = fmaxf(v0.y, 0.f);
                v1.x = fmaxf(v1.x, 0.f); v1.y = fmaxf(v1.y, 0.f);
            }
            *(float2*)(C + (size_t)row * NTOT + col)       = v0;
            *(float2*)(C + (size_t)(row + 8) * NTOT + col) = v1;
        }
    }
}

// ======================= adjacency build ========================================
__global__ void build_adj_kernel(const float* __restrict__ mask) {
    int warp = (blockIdx.x * blockDim.x + threadIdx.x) >> 5;
    int lane = threadIdx.x & 31;
    if (warp >= RB) return;
    const float* row = mask + (size_t)warp * NN;
    int cnt = 0;
    for (int j0 = 0; j0 < NN; j0 += 32) {
        int j = j0 + lane;
        bool on = (j < NN) && (row[j] > 0.5f);
        unsigned bal = __ballot_sync(0xffffffffu, on);
        if (on) {
            int pos = cnt + __popc(bal & ((1u << lane) - 1u));
            if (pos < MAXJ) g_adj[warp * MAXJ + pos] = j;
        }
        cnt += __popc(bal);
    }
    if (lane == 0) g_cnt[warp] = min(cnt, MAXJ);
}

// ======================= sparse attention (warp/row, online softmax) ============
__global__ void spattn_kernel(const float* __restrict__ vqk, float* __restrict__ out) {
    int warp = (blockIdx.x * blockDim.x + threadIdx.x) >> 5;
    int lane = threadIdx.x & 31;
    if (warp >= RB) return;
    int base = (warp / NN) * NN;
    float4 q4 = *(const float4*)(vqk + (size_t)warp * 384 + 128 + lane * 4);
    int cnt = g_cnt[warp];
    const int* adj = g_adj + warp * MAXJ;
    float m = -3.4e38f, l = 0.f;
    float4 acc = make_float4(0.f, 0.f, 0.f, 0.f);
    for (int t = 0; t < cnt; ++t) {
        size_t j = (size_t)(base + adj[t]) * 384;
        float4 k4 = *(const float4*)(vqk + j + 256 + lane * 4);
        float p = q4.x*k4.x + q4.y*k4.y + q4.z*k4.z + q4.w*k4.w;
        #pragma unroll
        for (int o = 16; o > 0; o >>= 1) p += __shfl_xor_sync(0xffffffffu, p, o);
        float4 v4 = *(const float4*)(vqk + j + lane * 4);
        float nm = fmaxf(m, p);
        float sc = __expf(m - nm);
        float e  = __expf(p - nm);
        l = l * sc + e;
        acc.x = acc.x * sc + e * v4.x;
        acc.y = acc.y * sc + e * v4.y;
        acc.z = acc.z * sc + e * v4.z;
        acc.w = acc.w * sc + e * v4.w;
        m = nm;
    }
    float inv = 1.f / l;
    float4 o4 = make_float4(acc.x*inv, acc.y*inv, acc.z*inv, acc.w*inv);
    *(float4*)(out + (size_t)warp * HH + lane * 4) = o4;
}

// ======================= GRU gate fusion ========================================
__global__ void gru_gate_kernel(const float* __restrict__ g1, const float* __restrict__ g2,
                                const float* __restrict__ hin, float* __restrict__ hout) {
    int idx = blockIdx.x * blockDim.x + threadIdx.x;
    if (idx >= RB * HH) return;
    int mrow = idx >> 7;
    int k = idx & 127;
    size_t b = (size_t)mrow * (3 * HH) + k;
    float xr = g1[b],           hr = g2[b];
    float xz = g1[b + HH],      hz = g2[b + HH];
    float xn = g1[b + 2 * HH],  hn = g2[b + 2 * HH];
    float r = 1.f / (1.f + __expf(-(xr + hr)));
    float z = 1.f / (1.f + __expf(-(xz + hz)));
    float n = tanhf(xn + r * hn);
    hout[idx] = (1.f - z) * n + z * hin[idx];
}

// ======================= FC head ================================================
__global__ void fc_kernel(const float* __restrict__ Hm, const float* __restrict__ W,
                          const float* __restrict__ bias, float* __restrict__ out) {
    __shared__ float Wt[AA * HH];
    __shared__ float bs[AA];
    int tid = threadIdx.x;
    for (int i = tid; i < AA * HH; i += blockDim.x) {
        int k = i / AA, a = i % AA;
        Wt[a * HH + k] = W[i];
    }
    if (tid < AA) bs[tid] = bias[tid];
    __syncthreads();
    int warp = (blockIdx.x * blockDim.x + tid) >> 5;
    int lane = tid & 31;
    if (warp >= RB) return;
    float4 h4 = *(const float4*)(Hm + (size_t)warp * HH + lane * 4);
    #pragma unroll
    for (int a = 0; a < AA; ++a) {
        float4 w4 = *(const float4*)(Wt + a * HH + lane * 4);
        float p = h4.x*w4.x + h4.y*w4.y + h4.z*w4.z + h4.w*w4.w;
        #pragma unroll
        for (int o = 16; o > 0; o >>= 1) p += __shfl_xor_sync(0xffffffffu, p, o);
        if (lane == 0) out[warp * AA + a] = p + bs[a];
    }
}

// ======================= launch =================================================
extern "C" void kernel_launch(void* const* d_in, const int* in_sizes, int n_in,
                              void* d_out, int out_size) {
    const float* x      = (const float*)d_in[0];
    const float* mask   = (const float*)d_in[1];
    const float* hidden = (const float*)d_in[2];
    const float* encW   = (const float*)d_in[3];
    const float* encb   = (const float*)d_in[4];
    const float* Wv1 = (const float*)d_in[5],  *bv1 = (const float*)d_in[6];
    const float* Wk1 = (const float*)d_in[7],  *bk1 = (const float*)d_in[8];
    const float* Wq1 = (const float*)d_in[9],  *bq1 = (const float*)d_in[10];
    const float* Wo1 = (const float*)d_in[11], *bo1 = (const float*)d_in[12];
    const float* Wv2 = (const float*)d_in[13], *bv2 = (const float*)d_in[14];
    const float* Wk2 = (const float*)d_in[15], *bk2 = (const float*)d_in[16];
    const float* Wq2 = (const float*)d_in[17], *bq2 = (const float*)d_in[18];
    const float* Wo2 = (const float*)d_in[19], *bo2 = (const float*)d_in[20];
    const float* Wih = (const float*)d_in[21], *bih = (const float*)d_in[22];
    const float* Whh = (const float*)d_in[23], *bhh = (const float*)d_in[24];
    const float* fcW = (const float*)d_in[25], *fcb = (const float*)d_in[26];

    float* out = (float*)d_out;
    float* qout = out;
    float* hout = out + (size_t)RB * AA;

    float *ph, *pt, *pg1, *pg2, *pbp1, *pbp2;
    uint4 *pBenc, *pBo1, *pBo2, *pBih, *pBhh, *pBv1, *pBv2;
    cudaGetSymbolAddress((void**)&ph,   g_h);
    cudaGetSymbolAddress((void**)&pt,   g_t);
    cudaGetSymbolAddress((void**)&pg1,  g_g1);
    cudaGetSymbolAddress((void**)&pg2,  g_g2);
    cudaGetSymbolAddress((void**)&pBenc, g_Benc);
    cudaGetSymbolAddress((void**)&pBo1,  g_Bo1);
    cudaGetSymbolAddress((void**)&pBo2,  g_Bo2);
    cudaGetSymbolAddress((void**)&pBih,  g_Bih);
    cudaGetSymbolAddress((void**)&pBhh,  g_Bhh);
    cudaGetSymbolAddress((void**)&pBv1,  g_Bv1);
    cudaGetSymbolAddress((void**)&pBv2,  g_Bv2);
    cudaGetSymbolAddress((void**)&pbp1,  g_bp1);
    cudaGetSymbolAddress((void**)&pbp2,  g_bp2);

    const int WB = 256;
    const int rowBlocks = RB / (WB / 32);     // 4000
    const int smemK128 = 128 * 64 * 4 * 2;    // 64 KB
    const int smemK64  = 128 * 32 * 4 * 2;    // 32 KB

    cudaFuncSetAttribute(mma_gemm_kernel<64,  true>,  cudaFuncAttributeMaxDynamicSharedMemorySize, smemK64);
    cudaFuncSetAttribute(mma_gemm_kernel<128, true>,  cudaFuncAttributeMaxDynamicSharedMemorySize, smemK128);
    cudaFuncSetAttribute(mma_gemm_kernel<128, false>, cudaFuncAttributeMaxDynamicSharedMemorySize, smemK128);

    // ---- weight fragment packing ----
    pack_frag_kernel<<<(4*16*32 + WB-1)/WB, WB>>>(encW, pBenc, 128, 64, 0);
    pack_frag_kernel<<<(8*16*32 + WB-1)/WB, WB>>>(Wo1,  pBo1,  128, 128, 0);
    pack_frag_kernel<<<(8*16*32 + WB-1)/WB, WB>>>(Wo2,  pBo2,  128, 128, 0);
    pack_frag_kernel<<<(8*48*32 + WB-1)/WB, WB>>>(Wih,  pBih,  384, 128, 1);
    pack_frag_kernel<<<(8*48*32 + WB-1)/WB, WB>>>(Whh,  pBhh,  384, 128, 1);
    pack_vqk_frag_kernel<<<(8*48*32 + WB-1)/WB, WB>>>(Wv1, Wq1, Wk1, bv1, bq1, bk1, pBv1, pbp1);
    pack_vqk_frag_kernel<<<(8*48*32 + WB-1)/WB, WB>>>(Wv2, Wq2, Wk2, bv2, bq2, bk2, pBv2, pbp2);
    build_adj_kernel<<<rowBlocks, WB>>>(mask);

    dim3 grid128(RB / 128, 1);   // (250,1)
    dim3 grid384(RB / 128, 3);   // (250,3)

    // encoder: h1 = relu(x @ encW + encb)
    mma_gemm_kernel<64, true><<<grid128, WB, smemK64>>>(x, pBenc, encb, ph, HH);

    // ---- attention layer 1 ----
    mma_gemm_kernel<128, true><<<grid384, WB, smemK128>>>(ph, pBv1, pbp1, pg1, 3*HH);
    spattn_kernel<<<rowBlocks, WB>>>(pg1, pt);
    mma_gemm_kernel<128, true><<<grid128, WB, smemK128>>>(pt, pBo1, bo1, ph, HH);

    // ---- attention layer 2 ----
    mma_gemm_kernel<128, true><<<grid384, WB, smemK128>>>(ph, pBv2, pbp2, pg1, 3*HH);
    spattn_kernel<<<rowBlocks, WB>>>(pg1, pt);
    mma_gemm_kernel<128, true><<<grid128, WB, smemK128>>>(pt, pBo2, bo2, ph, HH);

    // ---- GRU ----
    mma_gemm_kernel<128, false><<<grid384, WB, smemK128>>>(ph, pBih, bih, pg1, 3*HH);
    mma_gemm_kernel<128, false><<<grid384, WB, smemK128>>>(hidden, pBhh, bhh, pg2, 3*HH);
    gru_gate_kernel<<<(RB * HH + WB - 1) / WB, WB>>>(pg1, pg2, hidden, hout);

    // ---- head ----
    fc_kernel<<<rowBlocks, WB>>>(hout, fcW, fcb, qout);
    (void)in_sizes; (void)n_in; (void)out_size;
}

// round 8
// speedup vs baseline: 1.8413x; 1.1160x over previous
#include <cuda_runtime.h>
#include <cuda_bf16.h>
#include <cstdint>

// Problem constants
#define BB   32
#define NN   1000
#define DIN  64
#define HH   128
#define AA   10
#define RB   (BB*NN)          // 32000 rows
#define MAXJ 128

// ======================= scratch (static device globals) ========================
__device__ float g_h  [RB*HH];
__device__ float g_t  [RB*HH];
__device__ float g_g1 [RB*3*HH];
__device__ float g_g2 [RB*3*HH];
__device__ int   g_adj[RB*MAXJ];
__device__ int   g_cnt[RB];
// fragment-packed weights: uint4 per (kstep, ntile, lane) = {bh0,bh1,bl0,bl1}
// count = (K/16) * (N/8) * 32
__device__ uint4 g_Benc[4*16*32];      // K=64,  N=128
__device__ uint4 g_Bo1 [8*16*32];      // K=128, N=128
__device__ uint4 g_Bo2 [8*16*32];
__device__ uint4 g_Bih [8*48*32];      // K=128, N=384
__device__ uint4 g_Bhh [8*48*32];
__device__ uint4 g_Bv1 [8*48*32];
__device__ uint4 g_Bv2 [8*48*32];
__device__ float g_bp1 [3*HH];
__device__ float g_bp2 [3*HH];

// ======================= helpers ================================================
__device__ __forceinline__ void bsplit(float v, uint16_t& h, uint16_t& l) {
    __nv_bfloat16 bh = __float2bfloat16(v);
    float fh = __bfloat162float(bh);
    __nv_bfloat16 bl = __float2bfloat16(v - fh);
    h = __bfloat16_as_ushort(bh);
    l = __bfloat16_as_ushort(bl);
}
__device__ __forceinline__ uint32_t pk(uint16_t lo, uint16_t hi) {
    return ((uint32_t)hi << 16) | lo;
}
#define MMA_BF16(d, a, b0, b1)                                                   \
    asm volatile("mma.sync.aligned.m16n8k16.row.col.f32.bf16.bf16.f32 "          \
                 "{%0,%1,%2,%3}, {%4,%5,%6,%7}, {%8,%9}, {%0,%1,%2,%3};"         \
                 : "+f"((d)[0]), "+f"((d)[1]), "+f"((d)[2]), "+f"((d)[3])        \
                 : "r"((a)[0]), "r"((a)[1]), "r"((a)[2]), "r"((a)[3]),           \
                   "r"(b0), "r"(b1))

// ======================= weight fragment packing ================================
// For mma m16n8k16 col-major B: b0 = {B[k0][n], B[k0+1][n]}, b1 = rows k0+8,k0+9,
// k0 = ks*16 + (lane&3)*2, n = ntile*8 + (lane>>2).
__global__ void pack_frag_kernel(const float* __restrict__ W, uint4* __restrict__ Bp,
                                 int N, int K, int transb) {
    int i = blockIdx.x * blockDim.x + threadIdx.x;
    int NT = N >> 3, KS = K >> 4;
    if (i >= KS * NT * 32) return;
    int lane = i & 31, rest = i >> 5;
    int ntg = rest % NT, ks = rest / NT;
    int n = ntg * 8 + (lane >> 2);
    int k0 = ks * 16 + (lane & 3) * 2;
    float v[4];
    #pragma unroll
    for (int j = 0; j < 4; ++j) {
        int k = k0 + (j >> 1) * 8 + (j & 1);
        v[j] = transb ? W[n * K + k] : W[k * N + n];
    }
    uint16_t h[4], l[4];
    #pragma unroll
    for (int j = 0; j < 4; ++j) bsplit(v[j], h[j], l[j]);
    Bp[i] = make_uint4(pk(h[0], h[1]), pk(h[2], h[3]), pk(l[0], l[1]), pk(l[2], l[3]));
}

__global__ void pack_vqk_frag_kernel(const float* __restrict__ Wv, const float* __restrict__ Wq,
                                     const float* __restrict__ Wk, const float* __restrict__ bv,
                                     const float* __restrict__ bq, const float* __restrict__ bk,
                                     uint4* __restrict__ Bp, float* __restrict__ bp) {
    int i = blockIdx.x * blockDim.x + threadIdx.x;
    const int NT = 48, KS = 8, K = 128;
    if (i < HH) { bp[i] = bv[i]; bp[128 + i] = bq[i]; bp[256 + i] = bk[i]; }
    if (i >= KS * NT * 32) return;
    int lane = i & 31, rest = i >> 5;
    int ntg = rest % NT, ks = rest / NT;
    int n = ntg * 8 + (lane >> 2);
    const float* W = (n < 128) ? Wv : (n < 256) ? Wq : Wk;
    int nn = n & 127;
    int k0 = ks * 16 + (lane & 3) * 2;
    float v[4];
    #pragma unroll
    for (int j = 0; j < 4; ++j) {
        int k = k0 + (j >> 1) * 8 + (j & 1);
        v[j] = W[k * K + nn];             // Wv/Wq/Wk are [K=128, N=128] row-major
    }
    uint16_t h[4], l[4];
    #pragma unroll
    for (int j = 0; j < 4; ++j) bsplit(v[j], h[j], l[j]);
    Bp[i] = make_uint4(pk(h[0], h[1]), pk(h[2], h[3]), pk(l[0], l[1]), pk(l[2], l[3]));
}

// ======================= bf16x2 tensor-core GEMM ================================
// C[32000, NTOT] = relu?(A[32000,K] x B + bias), B pre-packed fragments.
// CTA tile 64x128, grid (500, NTOT/128). 8 warps = 2m x 4n, warp tile 32x32.
template<int K, bool RELU>
__global__ __launch_bounds__(256)
void mma_gemm_kernel(const float* __restrict__ A, const uint4* __restrict__ Bp,
                     const float* __restrict__ bias, float* __restrict__ C, int NTOT) {
    constexpr int KSTEPS = K / 16, KPAIRS = K / 2, F4R = K / 4;
    extern __shared__ uint32_t sA[];                  // Ah [64*KPAIRS] | Al [64*KPAIRS]
    uint32_t* Ah = sA;
    uint32_t* Al = sA + 64 * KPAIRS;
    const int tid = threadIdx.x, lane = tid & 31, wid = tid >> 5;
    const int mrow0 = blockIdx.x * 64, ncol0 = blockIdx.y * 128;

    // ---- convert A tile fp32 -> hi/lo bf16 pairs, XOR-swizzled ----
    #pragma unroll
    for (int c = 0; c < (64 * F4R) / 256; ++c) {
        int idx = tid + c * 256;
        int r = idx / F4R, q = idx % F4R;
        float4 v = *(const float4*)(A + (size_t)(mrow0 + r) * K + q * 4);
        uint16_t h0,l0,h1,l1,h2,l2,h3,l3;
        bsplit(v.x, h0, l0); bsplit(v.y, h1, l1);
        bsplit(v.z, h2, l2); bsplit(v.w, h3, l3);
        int p0 = q * 2, sw = (r & 7) << 2, base = r * KPAIRS;
        Ah[base + (p0 ^ sw)]       = pk(h0, h1);
        Ah[base + ((p0 + 1) ^ sw)] = pk(h2, h3);
        Al[base + (p0 ^ sw)]       = pk(l0, l1);
        Al[base + ((p0 + 1) ^ sw)] = pk(l2, l3);
    }
    __syncthreads();

    const int wm = wid & 1, wn = wid >> 1;
    const int g = lane >> 2, tg = lane & 3;
    const int NTtot = NTOT >> 3;
    const int ntbase = (ncol0 >> 3) + wn * 4;

    float acc[2][4][4];
    #pragma unroll
    for (int mt = 0; mt < 2; ++mt)
        #pragma unroll
        for (int nt = 0; nt < 4; ++nt)
            #pragma unroll
            for (int j = 0; j < 4; ++j) acc[mt][nt][j] = 0.f;

    #pragma unroll
    for (int ks = 0; ks < KSTEPS; ++ks) {
        uint32_t ah[2][4], al[2][4];
        #pragma unroll
        for (int mt = 0; mt < 2; ++mt) {
            int row = wm * 32 + mt * 16 + g;
            int sw = (row & 7) << 2;                  // (row+8)&7 == row&7
            int b0 = row * KPAIRS, b8 = (row + 8) * KPAIRS;
            int p0 = ks * 8 + tg;
            ah[mt][0] = Ah[b0 + (p0 ^ sw)];
            ah[mt][1] = Ah[b8 + (p0 ^ sw)];
            ah[mt][2] = Ah[b0 + ((p0 + 4) ^ sw)];
            ah[mt][3] = Ah[b8 + ((p0 + 4) ^ sw)];
            al[mt][0] = Al[b0 + (p0 ^ sw)];
            al[mt][1] = Al[b8 + (p0 ^ sw)];
            al[mt][2] = Al[b0 + ((p0 + 4) ^ sw)];
            al[mt][3] = Al[b8 + ((p0 + 4) ^ sw)];
        }
        #pragma unroll
        for (int nt = 0; nt < 4; ++nt) {
            uint4 b = Bp[(size_t)(ks * NTtot + ntbase + nt) * 32 + lane];
            #pragma unroll
            for (int mt = 0; mt < 2; ++mt) {
                MMA_BF16(acc[mt][nt], ah[mt], b.x, b.y);   // hi*hi
                MMA_BF16(acc[mt][nt], al[mt], b.x, b.y);   // lo*hi
                MMA_BF16(acc[mt][nt], ah[mt], b.z, b.w);   // hi*lo
            }
        }
    }

    // ---- epilogue: bias (+relu) + store ----
    #pragma unroll
    for (int mt = 0; mt < 2; ++mt) {
        int row = mrow0 + wm * 32 + mt * 16 + g;
        #pragma unroll
        for (int nt = 0; nt < 4; ++nt) {
            int col = ncol0 + wn * 32 + nt * 8 + tg * 2;
            float b0 = bias[col], b1 = bias[col + 1];
            float2 v0 = make_float2(acc[mt][nt][0] + b0, acc[mt][nt][1] + b1);
            float2 v1 = make_float2(acc[mt][nt][2] + b0, acc[mt][nt][3] + b1);
            if (RELU) {
                v0.x = fmaxf(v0.x, 0.f); v0.y = fmaxf(v0.y, 0.f);
                v1.x = fmaxf(v1.x, 0.f); v1.y = fmaxf(v1.y, 0.f);
            }
            *(float2*)(C + (size_t)row * NTOT + col)       = v0;
            *(float2*)(C + (size_t)(row + 8) * NTOT + col) = v1;
        }
    }
}

// ======================= adjacency build ========================================
__global__ void build_adj_kernel(const float* __restrict__ mask) {
    int warp = (blockIdx.x * blockDim.x + threadIdx.x) >> 5;
    int lane = threadIdx.x & 31;
    if (warp >= RB) return;
    const float* row = mask + (size_t)warp * NN;
    int cnt = 0;
    for (int j0 = 0; j0 < NN; j0 += 32) {
        int j = j0 + lane;
        bool on = (j < NN) && (row[j] > 0.5f);
        unsigned bal = __ballot_sync(0xffffffffu, on);
        if (on) {
            int pos = cnt + __popc(bal & ((1u << lane) - 1u));
            if (pos < MAXJ) g_adj[warp * MAXJ + pos] = j;
        }
        cnt += __popc(bal);
    }
    if (lane == 0) g_cnt[warp] = min(cnt, MAXJ);
}

// ======================= sparse attention (warp/row, online softmax) ============
__global__ void spattn_kernel(const float* __restrict__ vqk, float* __restrict__ out) {
    int warp = (blockIdx.x * blockDim.x + threadIdx.x) >> 5;
    int lane = threadIdx.x & 31;
    if (warp >= RB) return;
    int base = (warp / NN) * NN;
    float4 q4 = *(const float4*)(vqk + (size_t)warp * 384 + 128 + lane * 4);
    int cnt = g_cnt[warp];
    const int* adj = g_adj + warp * MAXJ;
    float m = -3.4e38f, l = 0.f;
    float4 acc = make_float4(0.f, 0.f, 0.f, 0.f);
    for (int t = 0; t < cnt; ++t) {
        size_t j = (size_t)(base + adj[t]) * 384;
        float4 k4 = *(const float4*)(vqk + j + 256 + lane * 4);
        float p = q4.x*k4.x + q4.y*k4.y + q4.z*k4.z + q4.w*k4.w;
        #pragma unroll
        for (int o = 16; o > 0; o >>= 1) p += __shfl_xor_sync(0xffffffffu, p, o);
        float4 v4 = *(const float4*)(vqk + j + lane * 4);
        float nm = fmaxf(m, p);
        float sc = __expf(m - nm);
        float e  = __expf(p - nm);
        l = l * sc + e;
        acc.x = acc.x * sc + e * v4.x;
        acc.y = acc.y * sc + e * v4.y;
        acc.z = acc.z * sc + e * v4.z;
        acc.w = acc.w * sc + e * v4.w;
        m = nm;
    }
    float inv = 1.f / l;
    float4 o4 = make_float4(acc.x*inv, acc.y*inv, acc.z*inv, acc.w*inv);
    *(float4*)(out + (size_t)warp * HH + lane * 4) = o4;
}

// ======================= GRU gate fusion (float4) ===============================
__global__ void gru_gate_kernel(const float* __restrict__ g1, const float* __restrict__ g2,
                                const float* __restrict__ hin, float* __restrict__ hout) {
    int idx = blockIdx.x * blockDim.x + threadIdx.x;   // over RB*HH/4
    if (idx >= RB * HH / 4) return;
    int mrow = idx >> 5;            // 32 float4 per row
    int k4 = (idx & 31) << 2;
    size_t b = (size_t)mrow * (3 * HH) + k4;
    float4 xr = *(const float4*)(g1 + b);
    float4 hr = *(const float4*)(g2 + b);
    float4 xz = *(const float4*)(g1 + b + HH);
    float4 hz = *(const float4*)(g2 + b + HH);
    float4 xn = *(const float4*)(g1 + b + 2 * HH);
    float4 hn = *(const float4*)(g2 + b + 2 * HH);
    float4 hi = *(const float4*)(hin + (size_t)mrow * HH + k4);
    float4 o;
    {
        float r = 1.f / (1.f + __expf(-(xr.x + hr.x)));
        float z = 1.f / (1.f + __expf(-(xz.x + hz.x)));
        float n = tanhf(xn.x + r * hn.x);
        o.x = (1.f - z) * n + z * hi.x;
    }
    {
        float r = 1.f / (1.f + __expf(-(xr.y + hr.y)));
        float z = 1.f / (1.f + __expf(-(xz.y + hz.y)));
        float n = tanhf(xn.y + r * hn.y);
        o.y = (1.f - z) * n + z * hi.y;
    }
    {
        float r = 1.f / (1.f + __expf(-(xr.z + hr.z)));
        float z = 1.f / (1.f + __expf(-(xz.z + hz.z)));
        float n = tanhf(xn.z + r * hn.z);
        o.z = (1.f - z) * n + z * hi.z;
    }
    {
        float r = 1.f / (1.f + __expf(-(xr.w + hr.w)));
        float z = 1.f / (1.f + __expf(-(xz.w + hz.w)));
        float n = tanhf(xn.w + r * hn.w);
        o.w = (1.f - z) * n + z * hi.w;
    }
    *(float4*)(hout + (size_t)mrow * HH + k4) = o;
}

// ======================= FC head ================================================
__global__ void fc_kernel(const float* __restrict__ Hm, const float* __restrict__ W,
                          const float* __restrict__ bias, float* __restrict__ out) {
    __shared__ float Wt[AA * HH];
    __shared__ float bs[AA];
    int tid = threadIdx.x;
    for (int i = tid; i < AA * HH; i += blockDim.x) {
        int k = i / AA, a = i % AA;
        Wt[a * HH + k] = W[i];
    }
    if (tid < AA) bs[tid] = bias[tid];
    __syncthreads();
    int warp = (blockIdx.x * blockDim.x + tid) >> 5;
    int lane = tid & 31;
    if (warp >= RB) return;
    float4 h4 = *(const float4*)(Hm + (size_t)warp * HH + lane * 4);
    #pragma unroll
    for (int a = 0; a < AA; ++a) {
        float4 w4 = *(const float4*)(Wt + a * HH + lane * 4);
        float p = h4.x*w4.x + h4.y*w4.y + h4.z*w4.z + h4.w*w4.w;
        #pragma unroll
        for (int o = 16; o > 0; o >>= 1) p += __shfl_xor_sync(0xffffffffu, p, o);
        if (lane == 0) out[warp * AA + a] = p + bs[a];
    }
}

// ======================= launch =================================================
extern "C" void kernel_launch(void* const* d_in, const int* in_sizes, int n_in,
                              void* d_out, int out_size) {
    const float* x      = (const float*)d_in[0];
    const float* mask   = (const float*)d_in[1];
    const float* hidden = (const float*)d_in[2];
    const float* encW   = (const float*)d_in[3];
    const float* encb   = (const float*)d_in[4];
    const float* Wv1 = (const float*)d_in[5],  *bv1 = (const float*)d_in[6];
    const float* Wk1 = (const float*)d_in[7],  *bk1 = (const float*)d_in[8];
    const float* Wq1 = (const float*)d_in[9],  *bq1 = (const float*)d_in[10];
    const float* Wo1 = (const float*)d_in[11], *bo1 = (const float*)d_in[12];
    const float* Wv2 = (const float*)d_in[13], *bv2 = (const float*)d_in[14];
    const float* Wk2 = (const float*)d_in[15], *bk2 = (const float*)d_in[16];
    const float* Wq2 = (const float*)d_in[17], *bq2 = (const float*)d_in[18];
    const float* Wo2 = (const float*)d_in[19], *bo2 = (const float*)d_in[20];
    const float* Wih = (const float*)d_in[21], *bih = (const float*)d_in[22];
    const float* Whh = (const float*)d_in[23], *bhh = (const float*)d_in[24];
    const float* fcW = (const float*)d_in[25], *fcb = (const float*)d_in[26];

    float* out = (float*)d_out;
    float* qout = out;
    float* hout = out + (size_t)RB * AA;

    float *ph, *pt, *pg1, *pg2, *pbp1, *pbp2;
    uint4 *pBenc, *pBo1, *pBo2, *pBih, *pBhh, *pBv1, *pBv2;
    cudaGetSymbolAddress((void**)&ph,   g_h);
    cudaGetSymbolAddress((void**)&pt,   g_t);
    cudaGetSymbolAddress((void**)&pg1,  g_g1);
    cudaGetSymbolAddress((void**)&pg2,  g_g2);
    cudaGetSymbolAddress((void**)&pBenc, g_Benc);
    cudaGetSymbolAddress((void**)&pBo1,  g_Bo1);
    cudaGetSymbolAddress((void**)&pBo2,  g_Bo2);
    cudaGetSymbolAddress((void**)&pBih,  g_Bih);
    cudaGetSymbolAddress((void**)&pBhh,  g_Bhh);
    cudaGetSymbolAddress((void**)&pBv1,  g_Bv1);
    cudaGetSymbolAddress((void**)&pBv2,  g_Bv2);
    cudaGetSymbolAddress((void**)&pbp1,  g_bp1);
    cudaGetSymbolAddress((void**)&pbp2,  g_bp2);

    const int WB = 256;
    const int rowBlocks = RB / (WB / 32);     // 4000
    const int smemK128 = 64 * 64 * 4 * 2;     // 32 KB
    const int smemK64  = 64 * 32 * 4 * 2;     // 16 KB

    cudaFuncSetAttribute(mma_gemm_kernel<64,  true>,  cudaFuncAttributeMaxDynamicSharedMemorySize, smemK64);
    cudaFuncSetAttribute(mma_gemm_kernel<128, true>,  cudaFuncAttributeMaxDynamicSharedMemorySize, smemK128);
    cudaFuncSetAttribute(mma_gemm_kernel<128, false>, cudaFuncAttributeMaxDynamicSharedMemorySize, smemK128);

    // ---- weight fragment packing ----
    pack_frag_kernel<<<(4*16*32 + WB-1)/WB, WB>>>(encW, pBenc, 128, 64, 0);
    pack_frag_kernel<<<(8*16*32 + WB-1)/WB, WB>>>(Wo1,  pBo1,  128, 128, 0);
    pack_frag_kernel<<<(8*16*32 + WB-1)/WB, WB>>>(Wo2,  pBo2,  128, 128, 0);
    pack_frag_kernel<<<(8*48*32 + WB-1)/WB, WB>>>(Wih,  pBih,  384, 128, 1);
    pack_frag_kernel<<<(8*48*32 + WB-1)/WB, WB>>>(Whh,  pBhh,  384, 128, 1);
    pack_vqk_frag_kernel<<<(8*48*32 + WB-1)/WB, WB>>>(Wv1, Wq1, Wk1, bv1, bq1, bk1, pBv1, pbp1);
    pack_vqk_frag_kernel<<<(8*48*32 + WB-1)/WB, WB>>>(Wv2, Wq2, Wk2, bv2, bq2, bk2, pBv2, pbp2);
    build_adj_kernel<<<rowBlocks, WB>>>(mask);

    dim3 grid128(RB / 64, 1);    // (500,1)
    dim3 grid384(RB / 64, 3);    // (500,3)

    // encoder: h1 = relu(x @ encW + encb)
    mma_gemm_kernel<64, true><<<grid128, WB, smemK64>>>(x, pBenc, encb, ph, HH);

    // ---- attention layer 1 ----
    mma_gemm_kernel<128, true><<<grid384, WB, smemK128>>>(ph, pBv1, pbp1, pg1, 3*HH);
    spattn_kernel<<<rowBlocks, WB>>>(pg1, pt);
    mma_gemm_kernel<128, true><<<grid128, WB, smemK128>>>(pt, pBo1, bo1, ph, HH);

    // ---- attention layer 2 ----
    mma_gemm_kernel<128, true><<<grid384, WB, smemK128>>>(ph, pBv2, pbp2, pg1, 3*HH);
    spattn_kernel<<<rowBlocks, WB>>>(pg1, pt);
    mma_gemm_kernel<128, true><<<grid128, WB, smemK128>>>(pt, pBo2, bo2, ph, HH);

    // ---- GRU ----
    mma_gemm_kernel<128, false><<<grid384, WB, smemK128>>>(ph, pBih, bih, pg1, 3*HH);
    mma_gemm_kernel<128, false><<<grid384, WB, smemK128>>>(hidden, pBhh, bhh, pg2, 3*HH);
    gru_gate_kernel<<<(RB * HH / 4 + WB - 1) / WB, WB>>>(pg1, pg2, hidden, hout);

    // ---- head ----
    fc_kernel<<<rowBlocks, WB>>>(hout, fcW, fcb, qout);
    (void)in_sizes; (void)n_in; (void)out_size;
}